// round 14
// baseline (speedup 1.0000x reference)
#include <cuda_runtime.h>
#include <cuda_fp16.h>
#include <cstdint>

typedef __half fp16;

#define S 2048
#define HID 2048
#define NH 16
#define NKV 2
#define HD 128
#define NREP 8
#define SCALE 0.08838834764831845f

// ---------------- scratch ----------------
__device__ __align__(16) fp16  g_hh[S * HID], g_hl[S * HID];           // hidden hi/lo
__device__ __align__(16) fp16  g_wqth[HID * HID], g_wqtl[HID * HID];   // Wq^T hi/lo [N][K]
__device__ __align__(16) fp16  g_wkth[256 * HID], g_wktl[256 * HID];   // Wk^T hi/lo
__device__ __align__(16) fp16  g_wvth[256 * HID];                      // Wv^T single
__device__ __align__(16) fp16  g_woth[HID * HID];                      // Wo^T single
__device__ __align__(16) fp16  g_qh[NH * S * HD], g_ql[NH * S * HD];   // rope'd Q (pre-scaled)
__device__ __align__(16) fp16  g_kh[NKV * S * HD], g_kl[NKV * S * HD];
__device__ __align__(16) fp16  g_vth[NKV * HD * S];                    // V^T single [D][S]
__device__ __align__(16) fp16  g_aoh[S * NH * HD], g_aol[S * NH * HD];

// ---------------- PTX helpers ----------------
__device__ __forceinline__ uint32_t smem_to_u32(const void* p) {
    uint32_t a;
    asm("{ .reg .u64 t; cvta.to.shared.u64 t, %1; cvt.u32.u64 %0, t; }" : "=r"(a) : "l"(p));
    return a;
}
#define CP_ASYNC16(dst, src) \
    asm volatile("cp.async.cg.shared.global [%0], [%1], 16;" :: "r"(dst), "l"(src))
#define CP_COMMIT() asm volatile("cp.async.commit_group;" ::: "memory")
#define CP_WAIT1() asm volatile("cp.async.wait_group 1;" ::: "memory")
#define CP_WAIT0() asm volatile("cp.async.wait_group 0;" ::: "memory")

__device__ __forceinline__ void ldsm_x4(uint32_t* r, uint32_t addr) {
    asm volatile("ldmatrix.sync.aligned.m8n8.x4.shared.b16 {%0,%1,%2,%3}, [%4];"
        : "=r"(r[0]), "=r"(r[1]), "=r"(r[2]), "=r"(r[3]) : "r"(addr));
}
__device__ __forceinline__ void mma_f16(float* c, const uint32_t* a, const uint32_t* b) {
    asm volatile("mma.sync.aligned.m16n8k16.row.col.f32.f16.f16.f32 "
        "{%0,%1,%2,%3}, {%4,%5,%6,%7}, {%8,%9}, {%0,%1,%2,%3};"
        : "+f"(c[0]), "+f"(c[1]), "+f"(c[2]), "+f"(c[3])
        : "r"(a[0]), "r"(a[1]), "r"(a[2]), "r"(a[3]), "r"(b[0]), "r"(b[1]));
}

// ============================================================================
// Dense GEMM accumulate core: 128x128 tile, BK=32, 2-stage cp.async (proven)
// 80 KB -> 2 CTAs/SM. Ends with __syncthreads (smem reusable by epilogue).
// ============================================================================
#define TILE_B 10240
#define STAGE_B 40960
#define SMEMSZ (2 * STAGE_B)

__device__ __forceinline__ void load_stage(
    uint32_t base,
    const fp16* __restrict__ Ah, const fp16* __restrict__ Al,
    const fp16* __restrict__ Bh, const fp16* __restrict__ Bl,
    int rowBase, int colBase, int k0, int lda, int ldb, int tid, int three)
{
    int lrow = tid >> 2, lc4 = tid & 3;
    #pragma unroll
    for (int r = 0; r < 2; r++) {
        int row = lrow + r * 64;
        uint32_t doff = row * 80 + lc4 * 16;
        int ke = k0 + lc4 * 8;
        CP_ASYNC16(base + 0 * TILE_B + doff, Ah + (long long)(rowBase + row) * lda + ke);
        CP_ASYNC16(base + 1 * TILE_B + doff, Al + (long long)(rowBase + row) * lda + ke);
        CP_ASYNC16(base + 2 * TILE_B + doff, Bh + (long long)(colBase + row) * ldb + ke);
        if (three)
            CP_ASYNC16(base + 3 * TILE_B + doff, Bl + (long long)(colBase + row) * ldb + ke);
    }
}

__device__ __forceinline__ void gemm_accum(
    const fp16* __restrict__ Ah, const fp16* __restrict__ Al,
    const fp16* __restrict__ Bh, const fp16* __restrict__ Bl,
    int rowBase, int colBase, int Klim, int lda, int ldb, int three,
    uint32_t sb, float c[4][4][4])
{
    int tid = threadIdx.x, wid = tid >> 5, lane = tid & 31;
    int wm = wid & 1, wn = wid >> 1;

    uint32_t aoff = (lane & 15) * 80 + ((lane >= 16) ? 16 : 0);
    uint32_t boff = ((lane & 7) + ((lane >= 16) ? 8 : 0)) * 80 + (((lane >> 3) & 1) ? 16 : 0);

    #pragma unroll
    for (int mi = 0; mi < 4; mi++)
        #pragma unroll
        for (int ni = 0; ni < 4; ni++)
            #pragma unroll
            for (int t = 0; t < 4; t++) c[mi][ni][t] = 0.f;

    int nst = Klim >> 5;
    load_stage(sb, Ah, Al, Bh, Bl, rowBase, colBase, 0, lda, ldb, tid, three);
    CP_COMMIT();

    for (int i = 0; i < nst; i++) {
        if (i + 1 < nst) {
            load_stage(sb + ((i + 1) & 1) * STAGE_B, Ah, Al, Bh, Bl,
                       rowBase, colBase, (i + 1) << 5, lda, ldb, tid, three);
            CP_COMMIT();
            CP_WAIT1();
        } else {
            CP_WAIT0();
        }
        __syncthreads();

        uint32_t base = sb + (i & 1) * STAGE_B;
        #pragma unroll
        for (int kk = 0; kk < 2; kk++) {
            uint32_t ah4[4][4], al4[4][4], bh4[2][4], bl4[2][4];
            #pragma unroll
            for (int mi = 0; mi < 4; mi++) {
                uint32_t ro = (64 * wm + 16 * mi) * 80 + kk * 32 + aoff;
                ldsm_x4(ah4[mi], base + 0 * TILE_B + ro);
                ldsm_x4(al4[mi], base + 1 * TILE_B + ro);
            }
            #pragma unroll
            for (int t = 0; t < 2; t++) {
                uint32_t ro = (32 * wn + 16 * t) * 80 + kk * 32 + boff;
                ldsm_x4(bh4[t], base + 2 * TILE_B + ro);
                if (three) ldsm_x4(bl4[t], base + 3 * TILE_B + ro);
            }
            #pragma unroll
            for (int mi = 0; mi < 4; mi++)
                #pragma unroll
                for (int ni = 0; ni < 4; ni++) {
                    uint32_t* bh = &bh4[ni >> 1][(ni & 1) * 2];
                    mma_f16(c[mi][ni], ah4[mi], bh);
                    mma_f16(c[mi][ni], al4[mi], bh);
                    if (three) {
                        uint32_t* bl = &bl4[ni >> 1][(ni & 1) * 2];
                        mma_f16(c[mi][ni], ah4[mi], bl);
                    }
                }
        }
        __syncthreads();
    }
}

// ---------------- output projection (standard fp32 epilogue) ----------------
__global__ __launch_bounds__(256) void gemm_mma(
    const fp16* Ah, const fp16* Al, const fp16* Bh,
    float* C, int K, int lda, int ldb, int ldc)
{
    extern __shared__ char smem[];
    uint32_t sb = smem_to_u32(smem);
    int rowBase = blockIdx.y * 128, colBase = blockIdx.x * 128;
    float c[4][4][4];
    gemm_accum(Ah, Al, Bh, Bh, rowBase, colBase, K, lda, ldb, 0, sb, c);

    int tid = threadIdx.x, wid = tid >> 5, lane = tid & 31;
    int wm = wid & 1, wn = wid >> 1;
    int g = lane >> 2, l4 = lane & 3;
    #pragma unroll
    for (int mi = 0; mi < 4; mi++)
        #pragma unroll
        for (int ni = 0; ni < 4; ni++) {
            int m = rowBase + 64 * wm + 16 * mi + g;
            int n = colBase + 32 * wn + 8 * ni + 2 * l4;
            float2 v0 = { c[mi][ni][0], c[mi][ni][1] };
            float2 v1 = { c[mi][ni][2], c[mi][ni][3] };
            *(float2*)&C[(long long)m * ldc + n] = v0;
            *(float2*)&C[(long long)(m + 8) * ldc + n] = v1;
        }
}

// ---------------- QKV projection with fused RoPE / V^T epilogue ----------------
// grid.x: 0..15 Q col-tiles (one head each), 16..17 K heads, 18..19 V heads
__global__ __launch_bounds__(256) void qkv_mma(
    const float* __restrict__ bq, const float* __restrict__ bk,
    const float* __restrict__ bv,
    const float* __restrict__ cs, const float* __restrict__ sn)
{
    extern __shared__ char smem[];
    uint32_t sb = smem_to_u32(smem);
    int bx = blockIdx.x;
    int rowBase = blockIdx.y * 128;

    const fp16 *Bh, *Bl; const float* bias; int ldb_n, cb, three, kind;
    if (bx < 16)      { Bh = g_wqth; Bl = g_wqtl; bias = bq; cb = bx;      three = 1; kind = 0; }
    else if (bx < 18) { Bh = g_wkth; Bl = g_wktl; bias = bk; cb = bx - 16; three = 1; kind = 1; }
    else              { Bh = g_wvth; Bl = g_wvth; bias = bv; cb = bx - 18; three = 0; kind = 2; }
    ldb_n = HID;

    float c[4][4][4];
    gemm_accum(g_hh, g_hl, Bh, Bl, rowBase, cb * 128, HID, HID, ldb_n, three, sb, c);

    // ---- stage fp32 tile (+bias) to smem: tile[128][132] ----
    float* tile = (float*)smem;
    int tid = threadIdx.x, wid = tid >> 5, lane = tid & 31;
    int wm = wid & 1, wn = wid >> 1;
    int g = lane >> 2, l4 = lane & 3;
    const float* biasB = bias + cb * 128;
    #pragma unroll
    for (int mi = 0; mi < 4; mi++)
        #pragma unroll
        for (int ni = 0; ni < 4; ni++) {
            int lm = 64 * wm + 16 * mi + g;
            int ln = 32 * wn + 8 * ni + 2 * l4;
            float b0 = biasB[ln], b1 = biasB[ln + 1];
            tile[lm * 132 + ln]           = c[mi][ni][0] + b0;
            tile[lm * 132 + ln + 1]       = c[mi][ni][1] + b1;
            tile[(lm + 8) * 132 + ln]     = c[mi][ni][2] + b0;
            tile[(lm + 8) * 132 + ln + 1] = c[mi][ni][3] + b1;
        }
    __syncthreads();

    if (kind != 2) {
        // RoPE: each 2 threads handle one row (s); halves of d
        fp16* oh = (kind == 0) ? g_qh : g_kh;
        fp16* ol = (kind == 0) ? g_ql : g_kl;
        float scl = (kind == 0) ? SCALE : 1.0f;
        int r = tid >> 1, h4 = (tid & 1) * 64;
        int s = rowBase + r;
        const float* csrow = cs + (s << 7);
        const float* snrow = sn + (s << 7);
        long long baseo = ((long long)cb * S + s) * HD + h4;
        const float* trow = tile + r * 132;
        #pragma unroll 8
        for (int dd = 0; dd < 64; dd += 2) {
            int d = h4 + dd;
            float x0 = trow[d],     x1 = trow[d + 1];
            float p0, p1;
            if (h4 == 0) { p0 = -trow[d + 64]; p1 = -trow[d + 65]; }
            else         { p0 =  trow[d - 64]; p1 =  trow[d - 63]; }
            float v0 = (x0 * csrow[d] + p0 * snrow[d]) * scl;
            float v1 = (x1 * csrow[d + 1] + p1 * snrow[d + 1]) * scl;
            __half2 hh = __floats2half2_rn(v0, v1);
            __half2 ll = __floats2half2_rn(v0 - __low2float(hh), v1 - __high2float(hh));
            *(__half2*)&oh[baseo + dd] = hh;
            *(__half2*)&ol[baseo + dd] = ll;
        }
    } else {
        // V: transposed write -> g_vth[(kvh*128+d)][s], single fp16
        int d = tid >> 1, h4 = (tid & 1) * 64;
        long long baseo = (long long)(cb * 128 + d) * S + rowBase + h4;
        #pragma unroll 8
        for (int ss = 0; ss < 64; ss += 2) {
            float v0 = tile[(h4 + ss) * 132 + d];
            float v1 = tile[(h4 + ss + 1) * 132 + d];
            *(__half2*)&g_vth[baseo + ss] = __floats2half2_rn(v0, v1);
        }
    }
}

// ============================================================================
// Flash attention (R11 proven): 256 CTAs, QK 3-term, PV 1-term
// ============================================================================
#define FQH  0
#define FQL  34816
#define FKV  69632
#define FKVB 53248
#define FKL  17408
#define FVH  34816
#define FSMEM (FKV + 2 * FKVB)

__device__ __forceinline__ void load_kv_tile(
    uint32_t dst, const fp16* __restrict__ Kh, const fp16* __restrict__ Kl,
    const fp16* __restrict__ Vh, int j, int tid)
{
    #pragma unroll
    for (int r = 0; r < 4; r++) {
        int idx = r * 256 + tid;
        int row = idx >> 4, c = idx & 15;
        uint32_t d = dst + row * 272 + c * 16;
        long long so = (long long)(j * 64 + row) * HD + c * 8;
        CP_ASYNC16(d, Kh + so);
        CP_ASYNC16(d + FKL, Kl + so);
    }
    #pragma unroll
    for (int r = 0; r < 4; r++) {
        int idx = r * 256 + tid;
        int row = idx >> 3, c = idx & 7;
        uint32_t d = dst + FVH + row * 144 + c * 16;
        long long so = (long long)row * S + j * 64 + c * 8;
        CP_ASYNC16(d, Vh + so);
    }
}

__global__ __launch_bounds__(256, 1) void flash_kernel()
{
    int bx = blockIdx.x;
    int h = bx & 15, rb = 15 - (bx >> 4);
    int kvh = h >> 3;

    const fp16* Qh = g_qh + ((long long)h * S + rb * 128) * HD;
    const fp16* Ql = g_ql + ((long long)h * S + rb * 128) * HD;
    const fp16* Kh = g_kh + (long long)kvh * S * HD;
    const fp16* Kl = g_kl + (long long)kvh * S * HD;
    const fp16* Vh = g_vth + (long long)kvh * HD * S;

    extern __shared__ char smem[];
    uint32_t sb = smem_to_u32(smem);
    int tid = threadIdx.x, wid = tid >> 5, lane = tid & 31;
    int g = lane >> 2, l4 = lane & 3;

    #pragma unroll
    for (int r = 0; r < 8; r++) {
        int idx = r * 256 + tid;
        int row = idx >> 4, c = idx & 15;
        uint32_t d = row * 272 + c * 16;
        long long so = (long long)row * HD + c * 8;
        CP_ASYNC16(sb + FQH + d, Qh + so);
        CP_ASYNC16(sb + FQL + d, Ql + so);
    }
    int nt = 2 * (rb + 1);
    load_kv_tile(sb + FKV, Kh, Kl, Vh, 0, tid);
    CP_COMMIT();

    float o[16][4];
    #pragma unroll
    for (int n = 0; n < 16; n++)
        #pragma unroll
        for (int t = 0; t < 4; t++) o[n][t] = 0.f;
    float mrow0 = -1e30f, mrow1 = -1e30f, lrow0 = 0.f, lrow1 = 0.f;

    uint32_t aoff = (lane & 15) * 272 + ((lane >= 16) ? 16 : 0);
    uint32_t boff = ((lane & 7) + ((lane >= 16) ? 8 : 0)) * 272 + ((lane >> 3) & 1) * 16;
    uint32_t voff = ((lane & 7) + ((lane >= 16) ? 8 : 0)) * 144 + ((lane >> 3) & 1) * 16;
    uint32_t qa_h = sb + FQH + wid * (16 * 272) + aoff;
    uint32_t qa_l = sb + FQL + wid * (16 * 272) + aoff;

    int row0 = rb * 128 + wid * 16 + g;

    for (int j = 0; j < nt; j++) {
        if (j + 1 < nt) {
            load_kv_tile(sb + FKV + ((j + 1) & 1) * FKVB, Kh, Kl, Vh, j + 1, tid);
            CP_COMMIT();
            CP_WAIT1();
        } else {
            CP_WAIT0();
        }
        __syncthreads();
        uint32_t kb = sb + FKV + (j & 1) * FKVB;

        // ---- QK^T (3-term) ----
        float sc[8][4];
        #pragma unroll
        for (int n = 0; n < 8; n++)
            #pragma unroll
            for (int t = 0; t < 4; t++) sc[n][t] = 0.f;

        #pragma unroll
        for (int kt = 0; kt < 8; kt++) {
            uint32_t ah[4], al[4];
            ldsm_x4(ah, qa_h + kt * 32);
            ldsm_x4(al, qa_l + kt * 32);
            #pragma unroll
            for (int p = 0; p < 4; p++) {
                uint32_t bh[4], bl[4];
                ldsm_x4(bh, kb + boff + p * (16 * 272) + kt * 32);
                ldsm_x4(bl, kb + FKL + boff + p * (16 * 272) + kt * 32);
                mma_f16(sc[2 * p],     ah, &bh[0]);
                mma_f16(sc[2 * p],     ah, &bl[0]);
                mma_f16(sc[2 * p],     al, &bh[0]);
                mma_f16(sc[2 * p + 1], ah, &bh[2]);
                mma_f16(sc[2 * p + 1], ah, &bl[2]);
                mma_f16(sc[2 * p + 1], al, &bh[2]);
            }
        }

        // ---- causal mask ----
        if (j >= 2 * rb) {
            int colb = j * 64 + 2 * l4;
            #pragma unroll
            for (int n = 0; n < 8; n++) {
                int c0 = colb + 8 * n;
                if (c0 > row0)     sc[n][0] = -1e30f;
                if (c0 + 1 > row0) sc[n][1] = -1e30f;
                if (c0 > row0 + 8)     sc[n][2] = -1e30f;
                if (c0 + 1 > row0 + 8) sc[n][3] = -1e30f;
            }
        }

        // ---- online softmax ----
        float mt0 = -1e30f, mt1 = -1e30f;
        #pragma unroll
        for (int n = 0; n < 8; n++) {
            mt0 = fmaxf(mt0, fmaxf(sc[n][0], sc[n][1]));
            mt1 = fmaxf(mt1, fmaxf(sc[n][2], sc[n][3]));
        }
        mt0 = fmaxf(mt0, __shfl_xor_sync(0xffffffff, mt0, 1));
        mt0 = fmaxf(mt0, __shfl_xor_sync(0xffffffff, mt0, 2));
        mt1 = fmaxf(mt1, __shfl_xor_sync(0xffffffff, mt1, 1));
        mt1 = fmaxf(mt1, __shfl_xor_sync(0xffffffff, mt1, 2));
        float mnew0 = fmaxf(mrow0, mt0), mnew1 = fmaxf(mrow1, mt1);
        float cf0 = __expf(mrow0 - mnew0), cf1 = __expf(mrow1 - mnew1);
        mrow0 = mnew0; mrow1 = mnew1;

        uint32_t pah[4][4];
        float rs0 = 0.f, rs1 = 0.f;
        #pragma unroll
        for (int t = 0; t < 4; t++) {
            #pragma unroll
            for (int e = 0; e < 2; e++) {
                int n = 2 * t + e;
                float p0 = __expf(sc[n][0] - mnew0);
                float p1 = __expf(sc[n][1] - mnew0);
                float p2 = __expf(sc[n][2] - mnew1);
                float p3 = __expf(sc[n][3] - mnew1);
                rs0 += p0 + p1; rs1 += p2 + p3;
                __half2 h01 = __floats2half2_rn(p0, p1);
                __half2 h23 = __floats2half2_rn(p2, p3);
                pah[t][2 * e]     = *(uint32_t*)&h01;
                pah[t][2 * e + 1] = *(uint32_t*)&h23;
            }
        }
        lrow0 = lrow0 * cf0 + rs0;
        lrow1 = lrow1 * cf1 + rs1;

        #pragma unroll
        for (int n = 0; n < 16; n++) {
            o[n][0] *= cf0; o[n][1] *= cf0;
            o[n][2] *= cf1; o[n][3] *= cf1;
        }

        // ---- P @ V (1-term) ----
        #pragma unroll
        for (int p = 0; p < 8; p++) {
            #pragma unroll
            for (int t = 0; t < 4; t++) {
                uint32_t vh[4];
                ldsm_x4(vh, kb + FVH + voff + p * (16 * 144) + t * 32);
                mma_f16(o[2 * p],     pah[t], &vh[0]);
                mma_f16(o[2 * p + 1], pah[t], &vh[2]);
            }
        }
        __syncthreads();
    }

    float ls0 = lrow0 + __shfl_xor_sync(0xffffffff, lrow0, 1);
    ls0 += __shfl_xor_sync(0xffffffff, ls0, 2);
    float ls1 = lrow1 + __shfl_xor_sync(0xffffffff, lrow1, 1);
    ls1 += __shfl_xor_sync(0xffffffff, ls1, 2);
    float inv0 = 1.0f / ls0, inv1 = 1.0f / ls1;

    #pragma unroll
    for (int n = 0; n < 16; n++) {
        int col = h * HD + n * 8 + 2 * l4;
        float v00 = o[n][0] * inv0, v01 = o[n][1] * inv0;
        float v10 = o[n][2] * inv1, v11 = o[n][3] * inv1;
        __half2 h0 = __floats2half2_rn(v00, v01);
        __half2 h1 = __floats2half2_rn(v10, v11);
        __half2 l0 = __floats2half2_rn(v00 - __low2float(h0), v01 - __high2float(h0));
        __half2 l1 = __floats2half2_rn(v10 - __low2float(h1), v11 - __high2float(h1));
        long long o0 = (long long)row0 * (NH * HD) + col;
        long long o1 = (long long)(row0 + 8) * (NH * HD) + col;
        *(__half2*)&g_aoh[o0] = h0; *(__half2*)&g_aol[o0] = l0;
        *(__half2*)&g_aoh[o1] = h1; *(__half2*)&g_aol[o1] = l1;
    }
}

// ---------------- preprocessing (one launch): weights + hidden split ----------------
__device__ __forceinline__ void transpose_core_xy(
    const float* __restrict__ in, fp16* __restrict__ oh, fp16* __restrict__ ol,
    int Kd, int Nd, int bxx, int byy, int x, int y)
{
    __shared__ float t[32][33];
    int nb = bxx * 32, kb = byy * 32;
    #pragma unroll
    for (int r = 0; r < 32; r += 8)
        t[y + r][x] = in[(long long)(kb + y + r) * Nd + nb + x];
    __syncthreads();
    #pragma unroll
    for (int r = 0; r < 32; r += 8) {
        int n = nb + y + r, k = kb + x;
        float v = t[x][y + r];
        fp16 h = __float2half_rn(v);
        oh[(long long)n * Kd + k] = h;
        if (ol) ol[(long long)n * Kd + k] = __float2half_rn(v - __half2float(h));
    }
}

// z=0 Wq, z=1 Wo, z=2 Wk(x<8)/Wv(8<=x<16), z=3 hidden hi/lo split
__global__ void prep_all(const float* __restrict__ hidden,
                         const float* __restrict__ Wq, const float* __restrict__ Wk,
                         const float* __restrict__ Wv, const float* __restrict__ Wo)
{
    int z = blockIdx.z;
    int x = threadIdx.x, y = threadIdx.y;
    if (z == 0) {
        transpose_core_xy(Wq, g_wqth, g_wqtl, HID, HID, blockIdx.x, blockIdx.y, x, y);
    } else if (z == 1) {
        transpose_core_xy(Wo, g_woth, nullptr, HID, HID, blockIdx.x, blockIdx.y, x, y);
    } else if (z == 2) {
        int bx = blockIdx.x;
        if (bx < 8)       transpose_core_xy(Wk, g_wkth, g_wktl, HID, 256, bx, blockIdx.y, x, y);
        else if (bx < 16) transpose_core_xy(Wv, g_wvth, nullptr, HID, 256, bx - 8, blockIdx.y, x, y);
    } else {
        int col = blockIdx.x * 32 + x, rowb = blockIdx.y * 32 + y;
        #pragma unroll
        for (int r = 0; r < 32; r += 8) {
            long long i = (long long)(rowb + r) * HID + col;
            float v = hidden[i];
            fp16 h = __float2half_rn(v);
            g_hh[i] = h;
            g_hl[i] = __float2half_rn(v - __half2float(h));
        }
    }
}

// ---------------- launch ----------------
extern "C" void kernel_launch(void* const* d_in, const int* in_sizes, int n_in,
                              void* d_out, int out_size)
{
    const float* hidden = (const float*)d_in[0];
    const float* cosb   = (const float*)d_in[1];
    const float* sinb   = (const float*)d_in[2];
    const float* Wq = (const float*)d_in[4];
    const float* bq = (const float*)d_in[5];
    const float* Wk = (const float*)d_in[6];
    const float* bk = (const float*)d_in[7];
    const float* Wv = (const float*)d_in[8];
    const float* bv = (const float*)d_in[9];
    const float* Wo = (const float*)d_in[10];
    float* out = (float*)d_out;

    cudaFuncSetAttribute(gemm_mma, cudaFuncAttributeMaxDynamicSharedMemorySize, SMEMSZ);
    cudaFuncSetAttribute(qkv_mma, cudaFuncAttributeMaxDynamicSharedMemorySize, SMEMSZ);
    cudaFuncSetAttribute(flash_kernel, cudaFuncAttributeMaxDynamicSharedMemorySize, FSMEM);

    fp16 *aoh, *aol, *woth;
    cudaGetSymbolAddress((void**)&aoh, g_aoh); cudaGetSymbolAddress((void**)&aol, g_aol);
    cudaGetSymbolAddress((void**)&woth, g_woth);

    dim3 tb(32, 8);

    // 0) weights transpose + hidden split (one launch)
    prep_all<<<dim3(64, 64, 4), tb>>>(hidden, Wq, Wk, Wv, Wo);

    // 1) fused QKV projection + RoPE + V^T (epilogue-fused)
    qkv_mma<<<dim3(20, 16), 256, SMEMSZ>>>(bq, bk, bv, cosb, sinb);

    // 2) flash attention (QK 3-term, PV 1-term; emits attn-out hi/lo)
    flash_kernel<<<256, 256, FSMEM>>>();

    // 3) output projection (2-term, Wo single fp16)
    gemm_mma<<<dim3(16, 16), 256, SMEMSZ>>>(aoh, aol, woth, out,
        HID, HID, HID, HID);
}

// round 15
// speedup vs baseline: 1.0718x; 1.0718x over previous
#include <cuda_runtime.h>
#include <cuda_fp16.h>
#include <cstdint>

typedef __half fp16;

#define S 2048
#define HID 2048
#define NH 16
#define NKV 2
#define HD 128
#define NREP 8
#define SCALE 0.08838834764831845f

// ---------------- scratch ----------------
__device__ __align__(16) fp16  g_hh[S * HID], g_hl[S * HID];           // hidden hi/lo
__device__ __align__(16) fp16  g_wqth[HID * HID], g_wqtl[HID * HID];   // Wq^T hi/lo [N][K]
__device__ __align__(16) fp16  g_wkth[256 * HID], g_wktl[256 * HID];   // Wk^T hi/lo
__device__ __align__(16) fp16  g_wvth[256 * HID];                      // Wv^T single
__device__ __align__(16) fp16  g_woth[HID * HID];                      // Wo^T single
__device__ float g_qp[S * NH * HD], g_kp[S * NKV * HD], g_vp[S * NKV * HD];
__device__ __align__(16) fp16  g_qh[NH * S * HD], g_ql[NH * S * HD];   // rope'd Q (pre-scaled)
__device__ __align__(16) fp16  g_kh[NKV * S * HD], g_kl[NKV * S * HD];
__device__ __align__(16) fp16  g_vth[NKV * HD * S];                    // V^T single [D][S]
__device__ __align__(16) fp16  g_aoh[S * NH * HD], g_aol[S * NH * HD];

// ---------------- PTX helpers ----------------
__device__ __forceinline__ uint32_t smem_to_u32(const void* p) {
    uint32_t a;
    asm("{ .reg .u64 t; cvta.to.shared.u64 t, %1; cvt.u32.u64 %0, t; }" : "=r"(a) : "l"(p));
    return a;
}
#define CP_ASYNC16(dst, src) \
    asm volatile("cp.async.cg.shared.global [%0], [%1], 16;" :: "r"(dst), "l"(src))
#define CP_COMMIT() asm volatile("cp.async.commit_group;" ::: "memory")
#define CP_WAIT2() asm volatile("cp.async.wait_group 2;" ::: "memory")
#define CP_WAIT1() asm volatile("cp.async.wait_group 1;" ::: "memory")
#define CP_WAIT0() asm volatile("cp.async.wait_group 0;" ::: "memory")

__device__ __forceinline__ void ldsm_x4(uint32_t* r, uint32_t addr) {
    asm volatile("ldmatrix.sync.aligned.m8n8.x4.shared.b16 {%0,%1,%2,%3}, [%4];"
        : "=r"(r[0]), "=r"(r[1]), "=r"(r[2]), "=r"(r[3]) : "r"(addr));
}
__device__ __forceinline__ void mma_f16(float* c, const uint32_t* a, const uint32_t* b) {
    asm volatile("mma.sync.aligned.m16n8k16.row.col.f32.f16.f16.f32 "
        "{%0,%1,%2,%3}, {%4,%5,%6,%7}, {%8,%9}, {%0,%1,%2,%3};"
        : "+f"(c[0]), "+f"(c[1]), "+f"(c[2]), "+f"(c[3])
        : "r"(a[0]), "r"(a[1]), "r"(a[2]), "r"(a[3]), "r"(b[0]), "r"(b[1]));
}

// ============================================================================
// QKV dense GEMM: 128x128 tile, BK=32, 2-stage cp.async (proven, 80 KB)
// ============================================================================
#define TILE_B 10240
#define STAGE_B 40960
#define SMEMSZ (2 * STAGE_B)

__device__ __forceinline__ void load_stage(
    uint32_t base,
    const fp16* __restrict__ Ah, const fp16* __restrict__ Al,
    const fp16* __restrict__ Bh, const fp16* __restrict__ Bl,
    int rowBase, int colBase, int k0, int lda, int ldb, int tid, int three)
{
    int lrow = tid >> 2, lc4 = tid & 3;
    #pragma unroll
    for (int r = 0; r < 2; r++) {
        int row = lrow + r * 64;
        uint32_t doff = row * 80 + lc4 * 16;
        int ke = k0 + lc4 * 8;
        CP_ASYNC16(base + 0 * TILE_B + doff, Ah + (long long)(rowBase + row) * lda + ke);
        CP_ASYNC16(base + 1 * TILE_B + doff, Al + (long long)(rowBase + row) * lda + ke);
        CP_ASYNC16(base + 2 * TILE_B + doff, Bh + (long long)(colBase + row) * ldb + ke);
        if (three)
            CP_ASYNC16(base + 3 * TILE_B + doff, Bl + (long long)(colBase + row) * ldb + ke);
    }
}

__device__ void gemm_mma_core(
    const fp16* __restrict__ Ah, const fp16* __restrict__ Al,
    const fp16* __restrict__ Bh, const fp16* __restrict__ Bl,
    const float* __restrict__ bias, float* __restrict__ C,
    int rowBase, int colBase, int Klim,
    int lda, int ldb, int ldc, float alpha, int three)
{
    extern __shared__ char smem[];
    uint32_t sb = smem_to_u32(smem);
    int tid = threadIdx.x, wid = tid >> 5, lane = tid & 31;
    int wm = wid & 1, wn = wid >> 1;

    uint32_t aoff = (lane & 15) * 80 + ((lane >= 16) ? 16 : 0);
    uint32_t boff = ((lane & 7) + ((lane >= 16) ? 8 : 0)) * 80 + (((lane >> 3) & 1) ? 16 : 0);

    float c[4][4][4];
    #pragma unroll
    for (int mi = 0; mi < 4; mi++)
        #pragma unroll
        for (int ni = 0; ni < 4; ni++)
            #pragma unroll
            for (int t = 0; t < 4; t++) c[mi][ni][t] = 0.f;

    int nst = Klim >> 5;
    load_stage(sb, Ah, Al, Bh, Bl, rowBase, colBase, 0, lda, ldb, tid, three);
    CP_COMMIT();

    for (int i = 0; i < nst; i++) {
        if (i + 1 < nst) {
            load_stage(sb + ((i + 1) & 1) * STAGE_B, Ah, Al, Bh, Bl,
                       rowBase, colBase, (i + 1) << 5, lda, ldb, tid, three);
            CP_COMMIT();
            CP_WAIT1();
        } else {
            CP_WAIT0();
        }
        __syncthreads();

        uint32_t base = sb + (i & 1) * STAGE_B;
        #pragma unroll
        for (int kk = 0; kk < 2; kk++) {
            uint32_t ah4[4][4], al4[4][4], bh4[2][4], bl4[2][4];
            #pragma unroll
            for (int mi = 0; mi < 4; mi++) {
                uint32_t ro = (64 * wm + 16 * mi) * 80 + kk * 32 + aoff;
                ldsm_x4(ah4[mi], base + 0 * TILE_B + ro);
                ldsm_x4(al4[mi], base + 1 * TILE_B + ro);
            }
            #pragma unroll
            for (int t = 0; t < 2; t++) {
                uint32_t ro = (32 * wn + 16 * t) * 80 + kk * 32 + boff;
                ldsm_x4(bh4[t], base + 2 * TILE_B + ro);
                if (three) ldsm_x4(bl4[t], base + 3 * TILE_B + ro);
            }
            #pragma unroll
            for (int mi = 0; mi < 4; mi++)
                #pragma unroll
                for (int ni = 0; ni < 4; ni++) {
                    uint32_t* bh = &bh4[ni >> 1][(ni & 1) * 2];
                    mma_f16(c[mi][ni], ah4[mi], bh);
                    mma_f16(c[mi][ni], al4[mi], bh);
                    if (three) {
                        uint32_t* bl = &bl4[ni >> 1][(ni & 1) * 2];
                        mma_f16(c[mi][ni], ah4[mi], bl);
                    }
                }
        }
        __syncthreads();
    }

    int g = lane >> 2, l4 = lane & 3;
    #pragma unroll
    for (int mi = 0; mi < 4; mi++)
        #pragma unroll
        for (int ni = 0; ni < 4; ni++) {
            int m = rowBase + 64 * wm + 16 * mi + g;
            int n = colBase + 32 * wn + 8 * ni + 2 * l4;
            float b0 = bias ? bias[n] : 0.f, b1 = bias ? bias[n + 1] : 0.f;
            float2 v0 = { c[mi][ni][0] * alpha + b0, c[mi][ni][1] * alpha + b1 };
            float2 v1 = { c[mi][ni][2] * alpha + b0, c[mi][ni][3] * alpha + b1 };
            *(float2*)&C[(long long)m * ldc + n] = v0;
            *(float2*)&C[(long long)(m + 8) * ldc + n] = v1;
        }
}

__global__ __launch_bounds__(256) void qkv_mma(
    const float* bq, const float* bk, const float* bv)
{
    int bx = blockIdx.x;
    const fp16 *Bh, *Bl; const float* bias; float* C; int ldc, cb, three;
    if (bx < 16)      { Bh = g_wqth; Bl = g_wqtl; bias = bq; C = g_qp; ldc = NH * HD;  cb = bx;      three = 1; }
    else if (bx < 18) { Bh = g_wkth; Bl = g_wktl; bias = bk; C = g_kp; ldc = NKV * HD; cb = bx - 16; three = 1; }
    else              { Bh = g_wvth; Bl = g_wvth; bias = bv; C = g_vp; ldc = NKV * HD; cb = bx - 18; three = 0; }
    gemm_mma_core(g_hh, g_hl, Bh, Bl, bias, C, blockIdx.y * 128, cb * 128, HID,
                  HID, HID, ldc, 1.0f, three);
}

// ============================================================================
// Output projection: 2-term, 3-stage cp.async pipeline (92 KB, 2 CTAs/SM)
// ============================================================================
#define OTILE_B 10240
#define OSTAGE_B 30720
#define OSMEM (3 * OSTAGE_B)

__device__ __forceinline__ void load_stage_o(
    uint32_t base, const fp16* __restrict__ Ah, const fp16* __restrict__ Al,
    const fp16* __restrict__ Bh, int rowBase, int colBase, int k0, int tid)
{
    int lrow = tid >> 2, lc4 = tid & 3;
    #pragma unroll
    for (int r = 0; r < 2; r++) {
        int row = lrow + r * 64;
        uint32_t doff = row * 80 + lc4 * 16;
        int ke = k0 + lc4 * 8;
        CP_ASYNC16(base + 0 * OTILE_B + doff, Ah + (long long)(rowBase + row) * HID + ke);
        CP_ASYNC16(base + 1 * OTILE_B + doff, Al + (long long)(rowBase + row) * HID + ke);
        CP_ASYNC16(base + 2 * OTILE_B + doff, Bh + (long long)(colBase + row) * HID + ke);
    }
}

__global__ __launch_bounds__(256, 2) void oproj_mma(
    const fp16* __restrict__ Ah, const fp16* __restrict__ Al,
    const fp16* __restrict__ Bh, float* __restrict__ C)
{
    extern __shared__ char smem[];
    uint32_t sb = smem_to_u32(smem);
    int rowBase = blockIdx.y * 128, colBase = blockIdx.x * 128;
    int tid = threadIdx.x, wid = tid >> 5, lane = tid & 31;
    int wm = wid & 1, wn = wid >> 1;

    uint32_t aoff = (lane & 15) * 80 + ((lane >= 16) ? 16 : 0);
    uint32_t boff = ((lane & 7) + ((lane >= 16) ? 8 : 0)) * 80 + (((lane >> 3) & 1) ? 16 : 0);

    float c[4][4][4];
    #pragma unroll
    for (int mi = 0; mi < 4; mi++)
        #pragma unroll
        for (int ni = 0; ni < 4; ni++)
            #pragma unroll
            for (int t = 0; t < 4; t++) c[mi][ni][t] = 0.f;

    const int nst = HID >> 5;   // 64
    load_stage_o(sb, Ah, Al, Bh, rowBase, colBase, 0, tid);
    CP_COMMIT();
    load_stage_o(sb + OSTAGE_B, Ah, Al, Bh, rowBase, colBase, 32, tid);
    CP_COMMIT();

    for (int i = 0; i < nst; i++) {
        if (i + 2 < nst)
            load_stage_o(sb + ((i + 2) % 3) * OSTAGE_B, Ah, Al, Bh,
                         rowBase, colBase, (i + 2) << 5, tid);
        CP_COMMIT();          // empty groups in the tail complete trivially
        CP_WAIT2();           // group i (current stage) is done
        __syncthreads();

        uint32_t base = sb + (i % 3) * OSTAGE_B;
        #pragma unroll
        for (int kk = 0; kk < 2; kk++) {
            uint32_t ah4[4][4], al4[4][4], bh4[2][4];
            #pragma unroll
            for (int mi = 0; mi < 4; mi++) {
                uint32_t ro = (64 * wm + 16 * mi) * 80 + kk * 32 + aoff;
                ldsm_x4(ah4[mi], base + 0 * OTILE_B + ro);
                ldsm_x4(al4[mi], base + 1 * OTILE_B + ro);
            }
            #pragma unroll
            for (int t = 0; t < 2; t++) {
                uint32_t ro = (32 * wn + 16 * t) * 80 + kk * 32 + boff;
                ldsm_x4(bh4[t], base + 2 * OTILE_B + ro);
            }
            #pragma unroll
            for (int mi = 0; mi < 4; mi++)
                #pragma unroll
                for (int ni = 0; ni < 4; ni++) {
                    uint32_t* bh = &bh4[ni >> 1][(ni & 1) * 2];
                    mma_f16(c[mi][ni], ah4[mi], bh);
                    mma_f16(c[mi][ni], al4[mi], bh);
                }
        }
        __syncthreads();
    }

    int g = lane >> 2, l4 = lane & 3;
    #pragma unroll
    for (int mi = 0; mi < 4; mi++)
        #pragma unroll
        for (int ni = 0; ni < 4; ni++) {
            int m = rowBase + 64 * wm + 16 * mi + g;
            int n = colBase + 32 * wn + 8 * ni + 2 * l4;
            float2 v0 = { c[mi][ni][0], c[mi][ni][1] };
            float2 v1 = { c[mi][ni][2], c[mi][ni][3] };
            *(float2*)&C[(long long)m * HID + n] = v0;
            *(float2*)&C[(long long)(m + 8) * HID + n] = v1;
        }
}

// ============================================================================
// Flash attention (R11 proven): 256 CTAs, QK 3-term, PV 1-term
// ============================================================================
#define FQH  0
#define FQL  34816
#define FKV  69632
#define FKVB 53248
#define FKL  17408
#define FVH  34816
#define FSMEM (FKV + 2 * FKVB)

__device__ __forceinline__ void load_kv_tile(
    uint32_t dst, const fp16* __restrict__ Kh, const fp16* __restrict__ Kl,
    const fp16* __restrict__ Vh, int j, int tid)
{
    #pragma unroll
    for (int r = 0; r < 4; r++) {
        int idx = r * 256 + tid;
        int row = idx >> 4, c = idx & 15;
        uint32_t d = dst + row * 272 + c * 16;
        long long so = (long long)(j * 64 + row) * HD + c * 8;
        CP_ASYNC16(d, Kh + so);
        CP_ASYNC16(d + FKL, Kl + so);
    }
    #pragma unroll
    for (int r = 0; r < 4; r++) {
        int idx = r * 256 + tid;
        int row = idx >> 3, c = idx & 7;
        uint32_t d = dst + FVH + row * 144 + c * 16;
        long long so = (long long)row * S + j * 64 + c * 8;
        CP_ASYNC16(d, Vh + so);
    }
}

__global__ __launch_bounds__(256, 1) void flash_kernel()
{
    int bx = blockIdx.x;
    int h = bx & 15, rb = 15 - (bx >> 4);
    int kvh = h >> 3;

    const fp16* Qh = g_qh + ((long long)h * S + rb * 128) * HD;
    const fp16* Ql = g_ql + ((long long)h * S + rb * 128) * HD;
    const fp16* Kh = g_kh + (long long)kvh * S * HD;
    const fp16* Kl = g_kl + (long long)kvh * S * HD;
    const fp16* Vh = g_vth + (long long)kvh * HD * S;

    extern __shared__ char smem[];
    uint32_t sb = smem_to_u32(smem);
    int tid = threadIdx.x, wid = tid >> 5, lane = tid & 31;
    int g = lane >> 2, l4 = lane & 3;

    #pragma unroll
    for (int r = 0; r < 8; r++) {
        int idx = r * 256 + tid;
        int row = idx >> 4, c = idx & 15;
        uint32_t d = row * 272 + c * 16;
        long long so = (long long)row * HD + c * 8;
        CP_ASYNC16(sb + FQH + d, Qh + so);
        CP_ASYNC16(sb + FQL + d, Ql + so);
    }
    int nt = 2 * (rb + 1);
    load_kv_tile(sb + FKV, Kh, Kl, Vh, 0, tid);
    CP_COMMIT();

    float o[16][4];
    #pragma unroll
    for (int n = 0; n < 16; n++)
        #pragma unroll
        for (int t = 0; t < 4; t++) o[n][t] = 0.f;
    float mrow0 = -1e30f, mrow1 = -1e30f, lrow0 = 0.f, lrow1 = 0.f;

    uint32_t aoff = (lane & 15) * 272 + ((lane >= 16) ? 16 : 0);
    uint32_t boff = ((lane & 7) + ((lane >= 16) ? 8 : 0)) * 272 + ((lane >> 3) & 1) * 16;
    uint32_t voff = ((lane & 7) + ((lane >= 16) ? 8 : 0)) * 144 + ((lane >> 3) & 1) * 16;
    uint32_t qa_h = sb + FQH + wid * (16 * 272) + aoff;
    uint32_t qa_l = sb + FQL + wid * (16 * 272) + aoff;

    int row0 = rb * 128 + wid * 16 + g;

    for (int j = 0; j < nt; j++) {
        if (j + 1 < nt) {
            load_kv_tile(sb + FKV + ((j + 1) & 1) * FKVB, Kh, Kl, Vh, j + 1, tid);
            CP_COMMIT();
            CP_WAIT1();
        } else {
            CP_WAIT0();
        }
        __syncthreads();
        uint32_t kb = sb + FKV + (j & 1) * FKVB;

        // ---- QK^T (3-term) ----
        float sc[8][4];
        #pragma unroll
        for (int n = 0; n < 8; n++)
            #pragma unroll
            for (int t = 0; t < 4; t++) sc[n][t] = 0.f;

        #pragma unroll
        for (int kt = 0; kt < 8; kt++) {
            uint32_t ah[4], al[4];
            ldsm_x4(ah, qa_h + kt * 32);
            ldsm_x4(al, qa_l + kt * 32);
            #pragma unroll
            for (int p = 0; p < 4; p++) {
                uint32_t bh[4], bl[4];
                ldsm_x4(bh, kb + boff + p * (16 * 272) + kt * 32);
                ldsm_x4(bl, kb + FKL + boff + p * (16 * 272) + kt * 32);
                mma_f16(sc[2 * p],     ah, &bh[0]);
                mma_f16(sc[2 * p],     ah, &bl[0]);
                mma_f16(sc[2 * p],     al, &bh[0]);
                mma_f16(sc[2 * p + 1], ah, &bh[2]);
                mma_f16(sc[2 * p + 1], ah, &bl[2]);
                mma_f16(sc[2 * p + 1], al, &bh[2]);
            }
        }

        // ---- causal mask ----
        if (j >= 2 * rb) {
            int colb = j * 64 + 2 * l4;
            #pragma unroll
            for (int n = 0; n < 8; n++) {
                int c0 = colb + 8 * n;
                if (c0 > row0)     sc[n][0] = -1e30f;
                if (c0 + 1 > row0) sc[n][1] = -1e30f;
                if (c0 > row0 + 8)     sc[n][2] = -1e30f;
                if (c0 + 1 > row0 + 8) sc[n][3] = -1e30f;
            }
        }

        // ---- online softmax ----
        float mt0 = -1e30f, mt1 = -1e30f;
        #pragma unroll
        for (int n = 0; n < 8; n++) {
            mt0 = fmaxf(mt0, fmaxf(sc[n][0], sc[n][1]));
            mt1 = fmaxf(mt1, fmaxf(sc[n][2], sc[n][3]));
        }
        mt0 = fmaxf(mt0, __shfl_xor_sync(0xffffffff, mt0, 1));
        mt0 = fmaxf(mt0, __shfl_xor_sync(0xffffffff, mt0, 2));
        mt1 = fmaxf(mt1, __shfl_xor_sync(0xffffffff, mt1, 1));
        mt1 = fmaxf(mt1, __shfl_xor_sync(0xffffffff, mt1, 2));
        float mnew0 = fmaxf(mrow0, mt0), mnew1 = fmaxf(mrow1, mt1);
        float cf0 = __expf(mrow0 - mnew0), cf1 = __expf(mrow1 - mnew1);
        mrow0 = mnew0; mrow1 = mnew1;

        uint32_t pah[4][4];
        float rs0 = 0.f, rs1 = 0.f;
        #pragma unroll
        for (int t = 0; t < 4; t++) {
            #pragma unroll
            for (int e = 0; e < 2; e++) {
                int n = 2 * t + e;
                float p0 = __expf(sc[n][0] - mnew0);
                float p1 = __expf(sc[n][1] - mnew0);
                float p2 = __expf(sc[n][2] - mnew1);
                float p3 = __expf(sc[n][3] - mnew1);
                rs0 += p0 + p1; rs1 += p2 + p3;
                __half2 h01 = __floats2half2_rn(p0, p1);
                __half2 h23 = __floats2half2_rn(p2, p3);
                pah[t][2 * e]     = *(uint32_t*)&h01;
                pah[t][2 * e + 1] = *(uint32_t*)&h23;
            }
        }
        lrow0 = lrow0 * cf0 + rs0;
        lrow1 = lrow1 * cf1 + rs1;

        #pragma unroll
        for (int n = 0; n < 16; n++) {
            o[n][0] *= cf0; o[n][1] *= cf0;
            o[n][2] *= cf1; o[n][3] *= cf1;
        }

        // ---- P @ V (1-term) ----
        #pragma unroll
        for (int p = 0; p < 8; p++) {
            #pragma unroll
            for (int t = 0; t < 4; t++) {
                uint32_t vh[4];
                ldsm_x4(vh, kb + FVH + voff + p * (16 * 144) + t * 32);
                mma_f16(o[2 * p],     pah[t], &vh[0]);
                mma_f16(o[2 * p + 1], pah[t], &vh[2]);
            }
        }
        __syncthreads();
    }

    float ls0 = lrow0 + __shfl_xor_sync(0xffffffff, lrow0, 1);
    ls0 += __shfl_xor_sync(0xffffffff, ls0, 2);
    float ls1 = lrow1 + __shfl_xor_sync(0xffffffff, lrow1, 1);
    ls1 += __shfl_xor_sync(0xffffffff, ls1, 2);
    float inv0 = 1.0f / ls0, inv1 = 1.0f / ls1;

    #pragma unroll
    for (int n = 0; n < 16; n++) {
        int col = h * HD + n * 8 + 2 * l4;
        float v00 = o[n][0] * inv0, v01 = o[n][1] * inv0;
        float v10 = o[n][2] * inv1, v11 = o[n][3] * inv1;
        __half2 h0 = __floats2half2_rn(v00, v01);
        __half2 h1 = __floats2half2_rn(v10, v11);
        __half2 l0 = __floats2half2_rn(v00 - __low2float(h0), v01 - __high2float(h0));
        __half2 l1 = __floats2half2_rn(v10 - __low2float(h1), v11 - __high2float(h1));
        long long o0 = (long long)row0 * (NH * HD) + col;
        long long o1 = (long long)(row0 + 8) * (NH * HD) + col;
        *(__half2*)&g_aoh[o0] = h0; *(__half2*)&g_aol[o0] = l0;
        *(__half2*)&g_aoh[o1] = h1; *(__half2*)&g_aol[o1] = l1;
    }
}

// ---------------- preprocessing (one launch): weights + hidden split ----------------
__device__ __forceinline__ void transpose_core_xy(
    const float* __restrict__ in, fp16* __restrict__ oh, fp16* __restrict__ ol,
    int Kd, int Nd, int bxx, int byy, int x, int y)
{
    __shared__ float t[32][33];
    int nb = bxx * 32, kb = byy * 32;
    #pragma unroll
    for (int r = 0; r < 32; r += 8)
        t[y + r][x] = in[(long long)(kb + y + r) * Nd + nb + x];
    __syncthreads();
    #pragma unroll
    for (int r = 0; r < 32; r += 8) {
        int n = nb + y + r, k = kb + x;
        float v = t[x][y + r];
        fp16 h = __float2half_rn(v);
        oh[(long long)n * Kd + k] = h;
        if (ol) ol[(long long)n * Kd + k] = __float2half_rn(v - __half2float(h));
    }
}

// z=0 Wq, z=1 Wo, z=2 Wk(x<8)/Wv(8<=x<16), z=3 hidden hi/lo split
__global__ void prep_all(const float* __restrict__ hidden,
                         const float* __restrict__ Wq, const float* __restrict__ Wk,
                         const float* __restrict__ Wv, const float* __restrict__ Wo)
{
    int z = blockIdx.z;
    int x = threadIdx.x, y = threadIdx.y;
    if (z == 0) {
        transpose_core_xy(Wq, g_wqth, g_wqtl, HID, HID, blockIdx.x, blockIdx.y, x, y);
    } else if (z == 1) {
        transpose_core_xy(Wo, g_woth, nullptr, HID, HID, blockIdx.x, blockIdx.y, x, y);
    } else if (z == 2) {
        int bx = blockIdx.x;
        if (bx < 8)       transpose_core_xy(Wk, g_wkth, g_wktl, HID, 256, bx, blockIdx.y, x, y);
        else if (bx < 16) transpose_core_xy(Wv, g_wvth, nullptr, HID, 256, bx - 8, blockIdx.y, x, y);
    } else {
        int col = blockIdx.x * 32 + x, rowb = blockIdx.y * 32 + y;
        #pragma unroll
        for (int r = 0; r < 32; r += 8) {
            long long i = (long long)(rowb + r) * HID + col;
            float v = hidden[i];
            fp16 h = __float2half_rn(v);
            g_hh[i] = h;
            g_hl[i] = __float2half_rn(v - __half2float(h));
        }
    }
}

// ---------------- mid (one launch): RoPE + V^T transpose ----------------
#define ROPE_BLOCKS ((NH + NKV) * S * HD / 256)
__global__ void mid_all(const float* __restrict__ cs, const float* __restrict__ sn)
{
    int bid = blockIdx.x;
    int tid = threadIdx.x;
    if (bid < ROPE_BLOCKS) {
        int idx = bid * 256 + tid;
        int d = idx & (HD - 1);
        int s = (idx >> 7) & (S - 1);
        int h = idx >> 18;

        float c  = cs[(s << 7) + d];
        float si = sn[(s << 7) + d];
        if (h < NH) {
            const float* row = g_qp + (long long)s * (NH * HD) + h * HD;
            float x = row[d];
            float r = (d < 64) ? -row[d + 64] : row[d - 64];
            float val = (x * c + r * si) * SCALE;
            long long o = ((long long)h * S + s) * HD + d;
            fp16 hh = __float2half_rn(val);
            g_qh[o] = hh;
            g_ql[o] = __float2half_rn(val - __half2float(hh));
        } else {
            int hk = h - NH;
            const float* row = g_kp + (long long)s * (NKV * HD) + hk * HD;
            float x = row[d];
            float r = (d < 64) ? -row[d + 64] : row[d - 64];
            float val = x * c + r * si;
            long long o = ((long long)hk * S + s) * HD + d;
            fp16 hh = __float2half_rn(val);
            g_kh[o] = hh;
            g_kl[o] = __float2half_rn(val - __half2float(hh));
        }
    } else {
        // V^T transpose: vp [S][256] fp32 -> g_vth [256][S] fp16
        int tb = bid - ROPE_BLOCKS;
        int bxx = tb & 7, byy = tb >> 3;
        transpose_core_xy(g_vp, g_vth, nullptr, S, 256, bxx, byy, tid & 31, tid >> 5);
    }
}

// ---------------- launch ----------------
extern "C" void kernel_launch(void* const* d_in, const int* in_sizes, int n_in,
                              void* d_out, int out_size)
{
    const float* hidden = (const float*)d_in[0];
    const float* cosb   = (const float*)d_in[1];
    const float* sinb   = (const float*)d_in[2];
    const float* Wq = (const float*)d_in[4];
    const float* bq = (const float*)d_in[5];
    const float* Wk = (const float*)d_in[6];
    const float* bk = (const float*)d_in[7];
    const float* Wv = (const float*)d_in[8];
    const float* bv = (const float*)d_in[9];
    const float* Wo = (const float*)d_in[10];
    float* out = (float*)d_out;

    cudaFuncSetAttribute(qkv_mma, cudaFuncAttributeMaxDynamicSharedMemorySize, SMEMSZ);
    cudaFuncSetAttribute(oproj_mma, cudaFuncAttributeMaxDynamicSharedMemorySize, OSMEM);
    cudaFuncSetAttribute(flash_kernel, cudaFuncAttributeMaxDynamicSharedMemorySize, FSMEM);

    fp16 *aoh, *aol, *woth;
    cudaGetSymbolAddress((void**)&aoh, g_aoh); cudaGetSymbolAddress((void**)&aol, g_aol);
    cudaGetSymbolAddress((void**)&woth, g_woth);

    dim3 tb(32, 8);

    // 0) weights transpose + hidden split (one launch)
    prep_all<<<dim3(64, 64, 4), tb>>>(hidden, Wq, Wk, Wv, Wo);

    // 1) fused QKV projection (Q/K 3-term, V 2-term)
    qkv_mma<<<dim3(20, 16), 256, SMEMSZ>>>(bq, bk, bv);

    // 2) RoPE + V^T transpose (one launch)
    mid_all<<<ROPE_BLOCKS + 512, 256>>>(cosb, sinb);

    // 3) flash attention (QK 3-term, PV 1-term; emits attn-out hi/lo)
    flash_kernel<<<256, 256, FSMEM>>>();

    // 4) output projection (2-term, 3-stage pipeline, 2 CTAs/SM)
    oproj_mma<<<dim3(16, 16), 256, OSMEM>>>(aoh, aol, woth, out);
}

// round 16
// speedup vs baseline: 1.0751x; 1.0031x over previous
#include <cuda_runtime.h>
#include <cuda_fp16.h>
#include <cstdint>

typedef __half fp16;

#define S 2048
#define HID 2048
#define NH 16
#define NKV 2
#define HD 128
#define NREP 8
#define SCALE 0.08838834764831845f

// ---------------- scratch ----------------
__device__ __align__(16) fp16  g_hh[S * HID], g_hl[S * HID];           // hidden hi/lo
__device__ __align__(16) fp16  g_wqth[HID * HID], g_wqtl[HID * HID];   // Wq^T hi/lo [N][K]
__device__ __align__(16) fp16  g_wkth[256 * HID], g_wktl[256 * HID];   // Wk^T hi/lo
__device__ __align__(16) fp16  g_wvth[256 * HID];                      // Wv^T single
__device__ __align__(16) fp16  g_woth[HID * HID];                      // Wo^T single
__device__ float g_qp[S * NH * HD], g_kp[S * NKV * HD], g_vp[S * NKV * HD];
__device__ __align__(16) fp16  g_qh[NH * S * HD], g_ql[NH * S * HD];   // rope'd Q (pre-scaled)
__device__ __align__(16) fp16  g_kh[NKV * S * HD], g_kl[NKV * S * HD];
__device__ __align__(16) fp16  g_vth[NKV * HD * S];                    // V^T single [D][S]
__device__ __align__(16) fp16  g_aoh[S * NH * HD], g_aol[S * NH * HD];

// ---------------- PTX helpers ----------------
__device__ __forceinline__ uint32_t smem_to_u32(const void* p) {
    uint32_t a;
    asm("{ .reg .u64 t; cvta.to.shared.u64 t, %1; cvt.u32.u64 %0, t; }" : "=r"(a) : "l"(p));
    return a;
}
#define CP_ASYNC16(dst, src) \
    asm volatile("cp.async.cg.shared.global [%0], [%1], 16;" :: "r"(dst), "l"(src))
#define CP_COMMIT() asm volatile("cp.async.commit_group;" ::: "memory")
#define CP_WAIT2() asm volatile("cp.async.wait_group 2;" ::: "memory")
#define CP_WAIT1() asm volatile("cp.async.wait_group 1;" ::: "memory")
#define CP_WAIT0() asm volatile("cp.async.wait_group 0;" ::: "memory")

__device__ __forceinline__ void ldsm_x4(uint32_t* r, uint32_t addr) {
    asm volatile("ldmatrix.sync.aligned.m8n8.x4.shared.b16 {%0,%1,%2,%3}, [%4];"
        : "=r"(r[0]), "=r"(r[1]), "=r"(r[2]), "=r"(r[3]) : "r"(addr));
}
__device__ __forceinline__ void mma_f16(float* c, const uint32_t* a, const uint32_t* b) {
    asm volatile("mma.sync.aligned.m16n8k16.row.col.f32.f16.f16.f32 "
        "{%0,%1,%2,%3}, {%4,%5,%6,%7}, {%8,%9}, {%0,%1,%2,%3};"
        : "+f"(c[0]), "+f"(c[1]), "+f"(c[2]), "+f"(c[3])
        : "r"(a[0]), "r"(a[1]), "r"(a[2]), "r"(a[3]), "r"(b[0]), "r"(b[1]));
}

// ============================================================================
// QKV dense GEMM: 128x128 tile, BK=32, 2-stage cp.async (proven, 80 KB)
// ============================================================================
#define TILE_B 10240
#define STAGE_B 40960
#define SMEMSZ (2 * STAGE_B)

__device__ __forceinline__ void load_stage(
    uint32_t base,
    const fp16* __restrict__ Ah, const fp16* __restrict__ Al,
    const fp16* __restrict__ Bh, const fp16* __restrict__ Bl,
    int rowBase, int colBase, int k0, int lda, int ldb, int tid, int three)
{
    int lrow = tid >> 2, lc4 = tid & 3;
    #pragma unroll
    for (int r = 0; r < 2; r++) {
        int row = lrow + r * 64;
        uint32_t doff = row * 80 + lc4 * 16;
        int ke = k0 + lc4 * 8;
        CP_ASYNC16(base + 0 * TILE_B + doff, Ah + (long long)(rowBase + row) * lda + ke);
        CP_ASYNC16(base + 1 * TILE_B + doff, Al + (long long)(rowBase + row) * lda + ke);
        CP_ASYNC16(base + 2 * TILE_B + doff, Bh + (long long)(colBase + row) * ldb + ke);
        if (three)
            CP_ASYNC16(base + 3 * TILE_B + doff, Bl + (long long)(colBase + row) * ldb + ke);
    }
}

__device__ void gemm_mma_core(
    const fp16* __restrict__ Ah, const fp16* __restrict__ Al,
    const fp16* __restrict__ Bh, const fp16* __restrict__ Bl,
    const float* __restrict__ bias, float* __restrict__ C,
    int rowBase, int colBase, int Klim,
    int lda, int ldb, int ldc, float alpha, int three)
{
    extern __shared__ char smem[];
    uint32_t sb = smem_to_u32(smem);
    int tid = threadIdx.x, wid = tid >> 5, lane = tid & 31;
    int wm = wid & 1, wn = wid >> 1;

    uint32_t aoff = (lane & 15) * 80 + ((lane >= 16) ? 16 : 0);
    uint32_t boff = ((lane & 7) + ((lane >= 16) ? 8 : 0)) * 80 + (((lane >> 3) & 1) ? 16 : 0);

    float c[4][4][4];
    #pragma unroll
    for (int mi = 0; mi < 4; mi++)
        #pragma unroll
        for (int ni = 0; ni < 4; ni++)
            #pragma unroll
            for (int t = 0; t < 4; t++) c[mi][ni][t] = 0.f;

    int nst = Klim >> 5;
    load_stage(sb, Ah, Al, Bh, Bl, rowBase, colBase, 0, lda, ldb, tid, three);
    CP_COMMIT();

    for (int i = 0; i < nst; i++) {
        if (i + 1 < nst) {
            load_stage(sb + ((i + 1) & 1) * STAGE_B, Ah, Al, Bh, Bl,
                       rowBase, colBase, (i + 1) << 5, lda, ldb, tid, three);
            CP_COMMIT();
            CP_WAIT1();
        } else {
            CP_WAIT0();
        }
        __syncthreads();

        uint32_t base = sb + (i & 1) * STAGE_B;
        #pragma unroll
        for (int kk = 0; kk < 2; kk++) {
            uint32_t ah4[4][4], al4[4][4], bh4[2][4], bl4[2][4];
            #pragma unroll
            for (int mi = 0; mi < 4; mi++) {
                uint32_t ro = (64 * wm + 16 * mi) * 80 + kk * 32 + aoff;
                ldsm_x4(ah4[mi], base + 0 * TILE_B + ro);
                ldsm_x4(al4[mi], base + 1 * TILE_B + ro);
            }
            #pragma unroll
            for (int t = 0; t < 2; t++) {
                uint32_t ro = (32 * wn + 16 * t) * 80 + kk * 32 + boff;
                ldsm_x4(bh4[t], base + 2 * TILE_B + ro);
                if (three) ldsm_x4(bl4[t], base + 3 * TILE_B + ro);
            }
            #pragma unroll
            for (int mi = 0; mi < 4; mi++)
                #pragma unroll
                for (int ni = 0; ni < 4; ni++) {
                    uint32_t* bh = &bh4[ni >> 1][(ni & 1) * 2];
                    mma_f16(c[mi][ni], ah4[mi], bh);
                    mma_f16(c[mi][ni], al4[mi], bh);
                    if (three) {
                        uint32_t* bl = &bl4[ni >> 1][(ni & 1) * 2];
                        mma_f16(c[mi][ni], ah4[mi], bl);
                    }
                }
        }
        __syncthreads();
    }

    int g = lane >> 2, l4 = lane & 3;
    #pragma unroll
    for (int mi = 0; mi < 4; mi++)
        #pragma unroll
        for (int ni = 0; ni < 4; ni++) {
            int m = rowBase + 64 * wm + 16 * mi + g;
            int n = colBase + 32 * wn + 8 * ni + 2 * l4;
            float b0 = bias ? bias[n] : 0.f, b1 = bias ? bias[n + 1] : 0.f;
            float2 v0 = { c[mi][ni][0] * alpha + b0, c[mi][ni][1] * alpha + b1 };
            float2 v1 = { c[mi][ni][2] * alpha + b0, c[mi][ni][3] * alpha + b1 };
            *(float2*)&C[(long long)m * ldc + n] = v0;
            *(float2*)&C[(long long)(m + 8) * ldc + n] = v1;
        }
}

__global__ __launch_bounds__(256) void qkv_mma(
    const float* bq, const float* bk, const float* bv)
{
    int bx = blockIdx.x;
    const fp16 *Bh, *Bl; const float* bias; float* C; int ldc, cb, three;
    if (bx < 16)      { Bh = g_wqth; Bl = g_wqtl; bias = bq; C = g_qp; ldc = NH * HD;  cb = bx;      three = 1; }
    else if (bx < 18) { Bh = g_wkth; Bl = g_wktl; bias = bk; C = g_kp; ldc = NKV * HD; cb = bx - 16; three = 1; }
    else              { Bh = g_wvth; Bl = g_wvth; bias = bv; C = g_vp; ldc = NKV * HD; cb = bx - 18; three = 0; }
    gemm_mma_core(g_hh, g_hl, Bh, Bl, bias, C, blockIdx.y * 128, cb * 128, HID,
                  HID, HID, ldc, 1.0f, three);
}

// ============================================================================
// Output projection: 2-term, 3-stage cp.async pipeline (92 KB, 2 CTAs/SM)
// ============================================================================
#define OTILE_B 10240
#define OSTAGE_B 30720
#define OSMEM (3 * OSTAGE_B)

__device__ __forceinline__ void load_stage_o(
    uint32_t base, const fp16* __restrict__ Ah, const fp16* __restrict__ Al,
    const fp16* __restrict__ Bh, int rowBase, int colBase, int k0, int tid)
{
    int lrow = tid >> 2, lc4 = tid & 3;
    #pragma unroll
    for (int r = 0; r < 2; r++) {
        int row = lrow + r * 64;
        uint32_t doff = row * 80 + lc4 * 16;
        int ke = k0 + lc4 * 8;
        CP_ASYNC16(base + 0 * OTILE_B + doff, Ah + (long long)(rowBase + row) * HID + ke);
        CP_ASYNC16(base + 1 * OTILE_B + doff, Al + (long long)(rowBase + row) * HID + ke);
        CP_ASYNC16(base + 2 * OTILE_B + doff, Bh + (long long)(colBase + row) * HID + ke);
    }
}

__global__ __launch_bounds__(256, 2) void oproj_mma(
    const fp16* __restrict__ Ah, const fp16* __restrict__ Al,
    const fp16* __restrict__ Bh, float* __restrict__ C)
{
    extern __shared__ char smem[];
    uint32_t sb = smem_to_u32(smem);
    int rowBase = blockIdx.y * 128, colBase = blockIdx.x * 128;
    int tid = threadIdx.x, wid = tid >> 5, lane = tid & 31;
    int wm = wid & 1, wn = wid >> 1;

    uint32_t aoff = (lane & 15) * 80 + ((lane >= 16) ? 16 : 0);
    uint32_t boff = ((lane & 7) + ((lane >= 16) ? 8 : 0)) * 80 + (((lane >> 3) & 1) ? 16 : 0);

    float c[4][4][4];
    #pragma unroll
    for (int mi = 0; mi < 4; mi++)
        #pragma unroll
        for (int ni = 0; ni < 4; ni++)
            #pragma unroll
            for (int t = 0; t < 4; t++) c[mi][ni][t] = 0.f;

    const int nst = HID >> 5;   // 64
    load_stage_o(sb, Ah, Al, Bh, rowBase, colBase, 0, tid);
    CP_COMMIT();
    load_stage_o(sb + OSTAGE_B, Ah, Al, Bh, rowBase, colBase, 32, tid);
    CP_COMMIT();

    for (int i = 0; i < nst; i++) {
        if (i + 2 < nst)
            load_stage_o(sb + ((i + 2) % 3) * OSTAGE_B, Ah, Al, Bh,
                         rowBase, colBase, (i + 2) << 5, tid);
        CP_COMMIT();
        CP_WAIT2();
        __syncthreads();

        uint32_t base = sb + (i % 3) * OSTAGE_B;
        #pragma unroll
        for (int kk = 0; kk < 2; kk++) {
            uint32_t ah4[4][4], al4[4][4], bh4[2][4];
            #pragma unroll
            for (int mi = 0; mi < 4; mi++) {
                uint32_t ro = (64 * wm + 16 * mi) * 80 + kk * 32 + aoff;
                ldsm_x4(ah4[mi], base + 0 * OTILE_B + ro);
                ldsm_x4(al4[mi], base + 1 * OTILE_B + ro);
            }
            #pragma unroll
            for (int t = 0; t < 2; t++) {
                uint32_t ro = (32 * wn + 16 * t) * 80 + kk * 32 + boff;
                ldsm_x4(bh4[t], base + 2 * OTILE_B + ro);
            }
            #pragma unroll
            for (int mi = 0; mi < 4; mi++)
                #pragma unroll
                for (int ni = 0; ni < 4; ni++) {
                    uint32_t* bh = &bh4[ni >> 1][(ni & 1) * 2];
                    mma_f16(c[mi][ni], ah4[mi], bh);
                    mma_f16(c[mi][ni], al4[mi], bh);
                }
        }
        __syncthreads();
    }

    int g = lane >> 2, l4 = lane & 3;
    #pragma unroll
    for (int mi = 0; mi < 4; mi++)
        #pragma unroll
        for (int ni = 0; ni < 4; ni++) {
            int m = rowBase + 64 * wm + 16 * mi + g;
            int n = colBase + 32 * wn + 8 * ni + 2 * l4;
            float2 v0 = { c[mi][ni][0], c[mi][ni][1] };
            float2 v1 = { c[mi][ni][2], c[mi][ni][3] };
            *(float2*)&C[(long long)m * HID + n] = v0;
            *(float2*)&C[(long long)(m + 8) * HID + n] = v1;
        }
}

// ============================================================================
// Flash attention: 256 CTAs, QK 3-term, PV 1-term, 3-stage KV ring (224 KB)
// ============================================================================
#define FQH  0
#define FQL  34816
#define FKV  69632
#define FKVB 53248
#define FKL  17408
#define FVH  34816
#define FSMEM (FKV + 3 * FKVB)

__device__ __forceinline__ void load_kv_tile(
    uint32_t dst, const fp16* __restrict__ Kh, const fp16* __restrict__ Kl,
    const fp16* __restrict__ Vh, int j, int tid)
{
    #pragma unroll
    for (int r = 0; r < 4; r++) {
        int idx = r * 256 + tid;
        int row = idx >> 4, c = idx & 15;
        uint32_t d = dst + row * 272 + c * 16;
        long long so = (long long)(j * 64 + row) * HD + c * 8;
        CP_ASYNC16(d, Kh + so);
        CP_ASYNC16(d + FKL, Kl + so);
    }
    #pragma unroll
    for (int r = 0; r < 4; r++) {
        int idx = r * 256 + tid;
        int row = idx >> 3, c = idx & 7;
        uint32_t d = dst + FVH + row * 144 + c * 16;
        long long so = (long long)row * S + j * 64 + c * 8;
        CP_ASYNC16(d, Vh + so);
    }
}

__global__ __launch_bounds__(256, 1) void flash_kernel()
{
    int bx = blockIdx.x;
    int h = bx & 15, rb = 15 - (bx >> 4);
    int kvh = h >> 3;

    const fp16* Qh = g_qh + ((long long)h * S + rb * 128) * HD;
    const fp16* Ql = g_ql + ((long long)h * S + rb * 128) * HD;
    const fp16* Kh = g_kh + (long long)kvh * S * HD;
    const fp16* Kl = g_kl + (long long)kvh * S * HD;
    const fp16* Vh = g_vth + (long long)kvh * HD * S;

    extern __shared__ char smem[];
    uint32_t sb = smem_to_u32(smem);
    int tid = threadIdx.x, wid = tid >> 5, lane = tid & 31;
    int g = lane >> 2, l4 = lane & 3;

    int nt = 2 * (rb + 1);

    // group 0: Q + kv0
    #pragma unroll
    for (int r = 0; r < 8; r++) {
        int idx = r * 256 + tid;
        int row = idx >> 4, c = idx & 15;
        uint32_t d = row * 272 + c * 16;
        long long so = (long long)row * HD + c * 8;
        CP_ASYNC16(sb + FQH + d, Qh + so);
        CP_ASYNC16(sb + FQL + d, Ql + so);
    }
    load_kv_tile(sb + FKV, Kh, Kl, Vh, 0, tid);
    CP_COMMIT();
    // group 1: kv1 (nt >= 2 always)
    load_kv_tile(sb + FKV + FKVB, Kh, Kl, Vh, 1, tid);
    CP_COMMIT();

    float o[16][4];
    #pragma unroll
    for (int n = 0; n < 16; n++)
        #pragma unroll
        for (int t = 0; t < 4; t++) o[n][t] = 0.f;
    float mrow0 = -1e30f, mrow1 = -1e30f, lrow0 = 0.f, lrow1 = 0.f;

    uint32_t aoff = (lane & 15) * 272 + ((lane >= 16) ? 16 : 0);
    uint32_t boff = ((lane & 7) + ((lane >= 16) ? 8 : 0)) * 272 + ((lane >> 3) & 1) * 16;
    uint32_t voff = ((lane & 7) + ((lane >= 16) ? 8 : 0)) * 144 + ((lane >> 3) & 1) * 16;
    uint32_t qa_h = sb + FQH + wid * (16 * 272) + aoff;
    uint32_t qa_l = sb + FQL + wid * (16 * 272) + aoff;

    int row0 = rb * 128 + wid * 16 + g;

    for (int j = 0; j < nt; j++) {
        if (j + 2 < nt)
            load_kv_tile(sb + FKV + ((j + 2) % 3) * FKVB, Kh, Kl, Vh, j + 2, tid);
        CP_COMMIT();      // empty in tail; completes trivially
        CP_WAIT2();       // group j (tile j, and for j=0 also Q) resident
        __syncthreads();
        uint32_t kb = sb + FKV + (j % 3) * FKVB;

        // ---- QK^T (3-term) ----
        float sc[8][4];
        #pragma unroll
        for (int n = 0; n < 8; n++)
            #pragma unroll
            for (int t = 0; t < 4; t++) sc[n][t] = 0.f;

        #pragma unroll
        for (int kt = 0; kt < 8; kt++) {
            uint32_t ah[4], al[4];
            ldsm_x4(ah, qa_h + kt * 32);
            ldsm_x4(al, qa_l + kt * 32);
            #pragma unroll
            for (int p = 0; p < 4; p++) {
                uint32_t bh[4], bl[4];
                ldsm_x4(bh, kb + boff + p * (16 * 272) + kt * 32);
                ldsm_x4(bl, kb + FKL + boff + p * (16 * 272) + kt * 32);
                mma_f16(sc[2 * p],     ah, &bh[0]);
                mma_f16(sc[2 * p],     ah, &bl[0]);
                mma_f16(sc[2 * p],     al, &bh[0]);
                mma_f16(sc[2 * p + 1], ah, &bh[2]);
                mma_f16(sc[2 * p + 1], ah, &bl[2]);
                mma_f16(sc[2 * p + 1], al, &bh[2]);
            }
        }

        // ---- causal mask ----
        if (j >= 2 * rb) {
            int colb = j * 64 + 2 * l4;
            #pragma unroll
            for (int n = 0; n < 8; n++) {
                int c0 = colb + 8 * n;
                if (c0 > row0)     sc[n][0] = -1e30f;
                if (c0 + 1 > row0) sc[n][1] = -1e30f;
                if (c0 > row0 + 8)     sc[n][2] = -1e30f;
                if (c0 + 1 > row0 + 8) sc[n][3] = -1e30f;
            }
        }

        // ---- online softmax ----
        float mt0 = -1e30f, mt1 = -1e30f;
        #pragma unroll
        for (int n = 0; n < 8; n++) {
            mt0 = fmaxf(mt0, fmaxf(sc[n][0], sc[n][1]));
            mt1 = fmaxf(mt1, fmaxf(sc[n][2], sc[n][3]));
        }
        mt0 = fmaxf(mt0, __shfl_xor_sync(0xffffffff, mt0, 1));
        mt0 = fmaxf(mt0, __shfl_xor_sync(0xffffffff, mt0, 2));
        mt1 = fmaxf(mt1, __shfl_xor_sync(0xffffffff, mt1, 1));
        mt1 = fmaxf(mt1, __shfl_xor_sync(0xffffffff, mt1, 2));
        float mnew0 = fmaxf(mrow0, mt0), mnew1 = fmaxf(mrow1, mt1);
        float cf0 = __expf(mrow0 - mnew0), cf1 = __expf(mrow1 - mnew1);
        mrow0 = mnew0; mrow1 = mnew1;

        uint32_t pah[4][4];
        float rs0 = 0.f, rs1 = 0.f;
        #pragma unroll
        for (int t = 0; t < 4; t++) {
            #pragma unroll
            for (int e = 0; e < 2; e++) {
                int n = 2 * t + e;
                float p0 = __expf(sc[n][0] - mnew0);
                float p1 = __expf(sc[n][1] - mnew0);
                float p2 = __expf(sc[n][2] - mnew1);
                float p3 = __expf(sc[n][3] - mnew1);
                rs0 += p0 + p1; rs1 += p2 + p3;
                __half2 h01 = __floats2half2_rn(p0, p1);
                __half2 h23 = __floats2half2_rn(p2, p3);
                pah[t][2 * e]     = *(uint32_t*)&h01;
                pah[t][2 * e + 1] = *(uint32_t*)&h23;
            }
        }
        lrow0 = lrow0 * cf0 + rs0;
        lrow1 = lrow1 * cf1 + rs1;

        #pragma unroll
        for (int n = 0; n < 16; n++) {
            o[n][0] *= cf0; o[n][1] *= cf0;
            o[n][2] *= cf1; o[n][3] *= cf1;
        }

        // ---- P @ V (1-term) ----
        #pragma unroll
        for (int p = 0; p < 8; p++) {
            #pragma unroll
            for (int t = 0; t < 4; t++) {
                uint32_t vh[4];
                ldsm_x4(vh, kb + FVH + voff + p * (16 * 144) + t * 32);
                mma_f16(o[2 * p],     pah[t], &vh[0]);
                mma_f16(o[2 * p + 1], pah[t], &vh[2]);
            }
        }
        __syncthreads();
    }

    float ls0 = lrow0 + __shfl_xor_sync(0xffffffff, lrow0, 1);
    ls0 += __shfl_xor_sync(0xffffffff, ls0, 2);
    float ls1 = lrow1 + __shfl_xor_sync(0xffffffff, lrow1, 1);
    ls1 += __shfl_xor_sync(0xffffffff, ls1, 2);
    float inv0 = 1.0f / ls0, inv1 = 1.0f / ls1;

    #pragma unroll
    for (int n = 0; n < 16; n++) {
        int col = h * HD + n * 8 + 2 * l4;
        float v00 = o[n][0] * inv0, v01 = o[n][1] * inv0;
        float v10 = o[n][2] * inv1, v11 = o[n][3] * inv1;
        __half2 h0 = __floats2half2_rn(v00, v01);
        __half2 h1 = __floats2half2_rn(v10, v11);
        __half2 l0 = __floats2half2_rn(v00 - __low2float(h0), v01 - __high2float(h0));
        __half2 l1 = __floats2half2_rn(v10 - __low2float(h1), v11 - __high2float(h1));
        long long o0 = (long long)row0 * (NH * HD) + col;
        long long o1 = (long long)(row0 + 8) * (NH * HD) + col;
        *(__half2*)&g_aoh[o0] = h0; *(__half2*)&g_aol[o0] = l0;
        *(__half2*)&g_aoh[o1] = h1; *(__half2*)&g_aol[o1] = l1;
    }
}

// ---------------- preprocessing (one launch): weights + hidden split ----------------
__device__ __forceinline__ void transpose_core_xy(
    const float* __restrict__ in, fp16* __restrict__ oh, fp16* __restrict__ ol,
    int Kd, int Nd, int bxx, int byy, int x, int y)
{
    __shared__ float t[32][33];
    int nb = bxx * 32, kb = byy * 32;
    #pragma unroll
    for (int r = 0; r < 32; r += 8)
        t[y + r][x] = in[(long long)(kb + y + r) * Nd + nb + x];
    __syncthreads();
    #pragma unroll
    for (int r = 0; r < 32; r += 8) {
        int n = nb + y + r, k = kb + x;
        float v = t[x][y + r];
        fp16 h = __float2half_rn(v);
        oh[(long long)n * Kd + k] = h;
        if (ol) ol[(long long)n * Kd + k] = __float2half_rn(v - __half2float(h));
    }
}

// z=0 Wq, z=1 Wo, z=2 Wk(x<8)/Wv(8<=x<16), z=3 hidden hi/lo split
__global__ void prep_all(const float* __restrict__ hidden,
                         const float* __restrict__ Wq, const float* __restrict__ Wk,
                         const float* __restrict__ Wv, const float* __restrict__ Wo)
{
    int z = blockIdx.z;
    int x = threadIdx.x, y = threadIdx.y;
    if (z == 0) {
        transpose_core_xy(Wq, g_wqth, g_wqtl, HID, HID, blockIdx.x, blockIdx.y, x, y);
    } else if (z == 1) {
        transpose_core_xy(Wo, g_woth, nullptr, HID, HID, blockIdx.x, blockIdx.y, x, y);
    } else if (z == 2) {
        int bx = blockIdx.x;
        if (bx < 8)       transpose_core_xy(Wk, g_wkth, g_wktl, HID, 256, bx, blockIdx.y, x, y);
        else if (bx < 16) transpose_core_xy(Wv, g_wvth, nullptr, HID, 256, bx - 8, blockIdx.y, x, y);
    } else {
        int col = blockIdx.x * 32 + x, rowb = blockIdx.y * 32 + y;
        #pragma unroll
        for (int r = 0; r < 32; r += 8) {
            long long i = (long long)(rowb + r) * HID + col;
            float v = hidden[i];
            fp16 h = __float2half_rn(v);
            g_hh[i] = h;
            g_hl[i] = __float2half_rn(v - __half2float(h));
        }
    }
}

// ---------------- mid (one launch): RoPE + V^T transpose ----------------
#define ROPE_BLOCKS ((NH + NKV) * S * HD / 256)
__global__ void mid_all(const float* __restrict__ cs, const float* __restrict__ sn)
{
    int bid = blockIdx.x;
    int tid = threadIdx.x;
    if (bid < ROPE_BLOCKS) {
        int idx = bid * 256 + tid;
        int d = idx & (HD - 1);
        int s = (idx >> 7) & (S - 1);
        int h = idx >> 18;

        float c  = cs[(s << 7) + d];
        float si = sn[(s << 7) + d];
        if (h < NH) {
            const float* row = g_qp + (long long)s * (NH * HD) + h * HD;
            float x = row[d];
            float r = (d < 64) ? -row[d + 64] : row[d - 64];
            float val = (x * c + r * si) * SCALE;
            long long o = ((long long)h * S + s) * HD + d;
            fp16 hh = __float2half_rn(val);
            g_qh[o] = hh;
            g_ql[o] = __float2half_rn(val - __half2float(hh));
        } else {
            int hk = h - NH;
            const float* row = g_kp + (long long)s * (NKV * HD) + hk * HD;
            float x = row[d];
            float r = (d < 64) ? -row[d + 64] : row[d - 64];
            float val = x * c + r * si;
            long long o = ((long long)hk * S + s) * HD + d;
            fp16 hh = __float2half_rn(val);
            g_kh[o] = hh;
            g_kl[o] = __float2half_rn(val - __half2float(hh));
        }
    } else {
        // V^T transpose: vp [S][256] fp32 -> g_vth [256][S] fp16
        int tb = bid - ROPE_BLOCKS;
        int bxx = tb & 7, byy = tb >> 3;
        transpose_core_xy(g_vp, g_vth, nullptr, S, 256, bxx, byy, tid & 31, tid >> 5);
    }
}

// ---------------- launch ----------------
extern "C" void kernel_launch(void* const* d_in, const int* in_sizes, int n_in,
                              void* d_out, int out_size)
{
    const float* hidden = (const float*)d_in[0];
    const float* cosb   = (const float*)d_in[1];
    const float* sinb   = (const float*)d_in[2];
    const float* Wq = (const float*)d_in[4];
    const float* bq = (const float*)d_in[5];
    const float* Wk = (const float*)d_in[6];
    const float* bk = (const float*)d_in[7];
    const float* Wv = (const float*)d_in[8];
    const float* bv = (const float*)d_in[9];
    const float* Wo = (const float*)d_in[10];
    float* out = (float*)d_out;

    cudaFuncSetAttribute(qkv_mma, cudaFuncAttributeMaxDynamicSharedMemorySize, SMEMSZ);
    cudaFuncSetAttribute(oproj_mma, cudaFuncAttributeMaxDynamicSharedMemorySize, OSMEM);
    cudaFuncSetAttribute(flash_kernel, cudaFuncAttributeMaxDynamicSharedMemorySize, FSMEM);

    fp16 *aoh, *aol, *woth;
    cudaGetSymbolAddress((void**)&aoh, g_aoh); cudaGetSymbolAddress((void**)&aol, g_aol);
    cudaGetSymbolAddress((void**)&woth, g_woth);

    dim3 tb(32, 8);

    // 0) weights transpose + hidden split (one launch)
    prep_all<<<dim3(64, 64, 4), tb>>>(hidden, Wq, Wk, Wv, Wo);

    // 1) fused QKV projection (Q/K 3-term, V 2-term)
    qkv_mma<<<dim3(20, 16), 256, SMEMSZ>>>(bq, bk, bv);

    // 2) RoPE + V^T transpose (one launch)
    mid_all<<<ROPE_BLOCKS + 512, 256>>>(cosb, sinb);

    // 3) flash attention (3-stage KV ring; QK 3-term, PV 1-term)
    flash_kernel<<<256, 256, FSMEM>>>();

    // 4) output projection (2-term, 3-stage pipeline, 2 CTAs/SM)
    oproj_mma<<<dim3(16, 16), 256, OSMEM>>>(aoh, aol, woth, out);
}